// round 12
// baseline (speedup 1.0000x reference)
#include <cuda_runtime.h>
#include <cooperative_groups.h>

namespace cg = cooperative_groups;

// Problem constants
#define B_    128
#define T_    1024
#define H_    512
#define I_    64
#define KA    576              // augmented K = H + I
#define NCTA  128
#define NTHR  512
#define NWARP 16
#define HT    64               // h-rows per CTA
#define BT    8                // b-cols per CTA
#define KW    36               // k per warp (16 x 36 = 576)
#define C1    0.9f
#define C2    0.1f

// smem floats: stile[576][8] + hs[8][68] + red[16w][32lane][16]
#define STILE_F (KA * BT)              // 4608
#define HS_F    (BT * 68)              // 544 (pad 68: conflict-free update)
#define RED_F   (NWARP * 32 * 16)      // 8192
#define SMEM_FLOATS (STILE_F + HS_F + RED_F)
#define SMEM_BYTES  (SMEM_FLOATS * 4)

// ---- global scratch (__device__ globals: allocation-free rule) ----
__device__ float g_S[2][H_ * B_];          // double-buffered sigmoid(h)
__device__ float g_xT[T_ * I_ * B_];       // x transposed to [t][i][b]
__device__ unsigned int g_cnt[16 * 32];    // per-group barrier count (padded)
__device__ unsigned int g_gen[16 * 32];    // per-group barrier generation

__device__ __forceinline__ void fma2(unsigned long long &acc,
                                     unsigned long long a,
                                     unsigned long long b) {
    asm("fma.rn.f32x2 %0, %1, %2, %0;" : "+l"(acc) : "l"(a), "l"(b));
}

__device__ __forceinline__ unsigned long long dup2(float v) {
    unsigned long long r;
    asm("mov.b64 %0, {%1, %1};" : "=l"(r) : "f"(v));
    return r;
}

__device__ __forceinline__ float sigmoidf_(float x) {
    return 1.0f / (1.0f + __expf(-x));
}

// 8-CTA group barrier. Safe: cooperative launch guarantees co-residency.
__device__ __forceinline__ void group_barrier(int grp) {
    __threadfence();                       // release S stores to L2
    __syncthreads();
    if (threadIdx.x == 0) {
        volatile unsigned int* genp = &g_gen[grp * 32];
        unsigned int my = *genp;           // read BEFORE arriving
        if (atomicAdd(&g_cnt[grp * 32], 1u) == 7u) {
            g_cnt[grp * 32] = 0u;
            __threadfence();
            atomicAdd((unsigned int*)&g_gen[grp * 32], 1u);
        } else {
            while (*genp == my) { }
        }
        __threadfence();                   // acquire
    }
    __syncthreads();
}

__global__ void __launch_bounds__(NTHR, 1)
rnn_coop_kernel(const float* __restrict__ x,      // [B,T,I]
                const float* __restrict__ W_in,   // [H,I]
                const float* __restrict__ W_h,    // [H,H]
                const float* __restrict__ sigma,  // [H,T,B]
                const float* __restrict__ h0,     // [H,B]
                float* __restrict__ out)          // [B,T,H] ++ [H,B]
{
    extern __shared__ float sm[];
    float* stile = sm;                     // [KA][8]   staged S ++ x rows
    float* hs    = sm + STILE_F;           // [8][68]   h tile (b-major, padded)
    float* red   = sm + STILE_F + HS_F;    // [16w][32l][16] K-split partials
    float* ts    = red;                    // transpose scratch alias

    cg::grid_group grid = cg::this_grid();

    const int tid  = threadIdx.x;
    const int warp = tid >> 5;
    const int lane = tid & 31;
    const int cta  = blockIdx.x;
    const int h0r  = (cta >> 4) * HT;      // 8 h-tiles
    const int bt   = cta & 15;             // 16 b-tiles
    const int b0   = bt * BT;

    // ---- one-time: transpose x[B,T,I] -> g_xT[t][i][b] (first 256 threads)
    for (int tile = cta; tile < 8192; tile += NCTA) {
        int tb = tile & 3;
        int ti = (tile >> 2) & 1;
        int tt = tile >> 3;
        if (tid < 256) {   // load + transpose into ts[i][b] (pad 33)
            int row = tid >> 3;
            int c4  = tid & 7;
            float4 v = *(const float4*)(x + (size_t)(tb * 32 + row) * (T_ * I_)
                                          + (size_t)tt * I_ + ti * 32 + 4 * c4);
            ts[(4 * c4 + 0) * 33 + row] = v.x;
            ts[(4 * c4 + 1) * 33 + row] = v.y;
            ts[(4 * c4 + 2) * 33 + row] = v.z;
            ts[(4 * c4 + 3) * 33 + row] = v.w;
        }
        __syncthreads();
        if (tid < 256) {   // write coalesced
            int irow = tid >> 3;
            int b4   = tid & 7;
            float4 v;
            v.x = ts[irow * 33 + 4 * b4 + 0];
            v.y = ts[irow * 33 + 4 * b4 + 1];
            v.z = ts[irow * 33 + 4 * b4 + 2];
            v.w = ts[irow * 33 + 4 * b4 + 3];
            __stcg((float4*)(g_xT + ((size_t)tt * I_ + ti * 32 + irow) * B_
                                  + tb * 32 + 4 * b4), v);
        }
        __syncthreads();
    }

    // ---- one-time: load this thread's W slice into registers.
    // warp w covers k in [36w, 36w+36); lane l owns h rows (2l, 2l+1).
    float w0[KW], w1[KW];
    {
        const int kb = KW * warp;
        const int hA = h0r + 2 * lane, hB = hA + 1;
        #pragma unroll
        for (int j = 0; j < KW; ++j) {
            int k = kb + j;
            if (k < H_) {
                w0[j] = W_h[(size_t)hA * H_ + k];
                w1[j] = W_h[(size_t)hB * H_ + k];
            } else {
                w0[j] = W_in[(size_t)hA * I_ + k - H_];
                w1[j] = W_in[(size_t)hB * I_ + k - H_];
            }
        }
    }

    // ---- init h tile + publish sigmoid(h0) into buffer 0
    const int uh = tid >> 3;               // update-map h (0..63)
    const int ub = tid & 7;                // update-map b (0..7)
    {
        float h = h0[(size_t)(h0r + uh) * B_ + b0 + ub];
        hs[ub * 68 + uh] = h;
        __stcg(&g_S[0][(size_t)(h0r + uh) * B_ + b0 + ub], sigmoidf_(h));
    }
    grid.sync();                           // one global sync; groups hereafter

    int p = 0;
    for (int t = 0; t < T_; ++t) {
        // ---- stage stile[576][8]: S rows from g_S[p] (.cg), x rows from g_xT
        #pragma unroll
        for (int it = 0; it < 3; ++it) {   // 1152 float4 tasks
            int idx = it * NTHR + tid;
            if (idx < KA * 2) {
                int row = idx >> 1, q = (idx & 1) * 4;
                float4 v = (row < H_)
                    ? __ldcg((const float4*)(g_S[p] + (size_t)row * B_ + b0 + q))
                    : __ldcg((const float4*)(g_xT + ((size_t)t * I_ + row - H_) * B_ + b0 + q));
                *(float4*)(stile + row * BT + q) = v;
            }
        }
        // sigma prefetch for the update phase (1 value/thread)
        float sgv = __ldg(sigma + ((size_t)(h0r + uh) * T_ + t) * B_ + b0 + ub);
        __syncthreads();

        // ---- GEMM: warp covers 64h x 8b for its 36 k; W in registers.
        unsigned long long a0[4], a1[4];
        #pragma unroll
        for (int i = 0; i < 4; ++i) { a0[i] = 0ull; a1[i] = 0ull; }
        {
            const ulonglong2* sp = (const ulonglong2*)(stile + KW * warp * BT);
            #pragma unroll
            for (int j = 0; j < KW; ++j) {
                ulonglong2 sA = sp[2 * j];      // s[b0..b3] as 2x f32x2
                ulonglong2 sB = sp[2 * j + 1];  // s[b4..b7]
                unsigned long long wd0 = dup2(w0[j]);
                unsigned long long wd1 = dup2(w1[j]);
                fma2(a0[0], wd0, sA.x); fma2(a0[1], wd0, sA.y);
                fma2(a0[2], wd0, sB.x); fma2(a0[3], wd0, sB.y);
                fma2(a1[0], wd1, sA.x); fma2(a1[1], wd1, sA.y);
                fma2(a1[2], wd1, sB.x); fma2(a1[3], wd1, sB.y);
            }
        }

        // ---- store K-split partials: 64B block per (warp, lane)
        {
            ulonglong2* blk = (ulonglong2*)(red + (warp * 32 + lane) * 16);
            blk[0] = make_ulonglong2(a0[0], a0[1]);
            blk[1] = make_ulonglong2(a0[2], a0[3]);
            blk[2] = make_ulonglong2(a1[0], a1[1]);
            blk[3] = make_ulonglong2(a1[2], a1[3]);
        }
        __syncthreads();

        // ---- reduce 16 partials + leaky update (1 (h,b) cell per thread)
        {
            int hp = uh >> 1, hc = uh & 1, bp = ub >> 1, bc = ub & 1;
            int off = hc * 8 + bp * 2 + bc;
            float s = 0.f;
            #pragma unroll
            for (int w = 0; w < NWARP; ++w)
                s += red[(w * 32 + hp) * 16 + off];
            float hn = C1 * hs[ub * 68 + uh] + C2 * (s + sgv);
            hs[ub * 68 + uh] = hn;
            __stcg(&g_S[1 - p][(size_t)(h0r + uh) * B_ + b0 + ub], sigmoidf_(hn));
        }
        __syncthreads();

        // ---- coalesced out tile [B,T,H]: 1 float/thread, 128B per warp
        {
            int ob = tid >> 6, oh = tid & 63;
            out[((size_t)(b0 + ob) * T_ + t) * H_ + h0r + oh] = hs[ob * 68 + oh];
        }

        group_barrier(bt);                 // only the 8 CTAs sharing b-slice
        p ^= 1;
    }

    // ---- h_last [H,B] appended after out [B,T,H]
    out[(size_t)B_ * T_ * H_ + (size_t)(h0r + uh) * B_ + b0 + ub] = hs[ub * 68 + uh];
}

extern "C" void kernel_launch(void* const* d_in, const int* in_sizes, int n_in,
                              void* d_out, int out_size) {
    const float* x    = (const float*)d_in[0];
    const float* W_in = (const float*)d_in[1];
    const float* W_h  = (const float*)d_in[2];
    const float* sg   = (const float*)d_in[3];
    const float* h0   = (const float*)d_in[4];
    float* out = (float*)d_out;

    static int smem_set = 0;
    if (!smem_set) {
        cudaFuncSetAttribute(rnn_coop_kernel,
                             cudaFuncAttributeMaxDynamicSharedMemorySize, SMEM_BYTES);
        smem_set = 1;
    }

    cudaLaunchConfig_t cfg = {};
    cfg.gridDim  = dim3(NCTA, 1, 1);
    cfg.blockDim = dim3(NTHR, 1, 1);
    cfg.dynamicSmemBytes = SMEM_BYTES;
    cfg.stream = 0;
    cudaLaunchAttribute attr[1];
    attr[0].id = cudaLaunchAttributeCooperative;
    attr[0].val.cooperative = 1;
    cfg.attrs = attr;
    cfg.numAttrs = 1;

    cudaLaunchKernelEx(&cfg, rnn_coop_kernel, x, W_in, W_h, sg, h0, out);
}

// round 14
// speedup vs baseline: 1.1476x; 1.1476x over previous
#include <cuda_runtime.h>
#include <cooperative_groups.h>

namespace cg = cooperative_groups;

// Problem constants
#define B_    128
#define T_    1024
#define H_    512
#define I_    64
#define KA    576              // augmented K = H + I
#define NCTA  128
#define NTHR  512
#define NWARP 16
#define HT    32               // h-rows per CTA
#define BT    16               // b-cols per CTA
#define KW    36               // k per warp (16 x 36 = 576)
#define C1    0.9f
#define C2    0.1f

// smem floats: wtile[KA][32] + stile[KA][16] + hs[32][17] + red[16][32][16]
#define WT_F  (KA * 32)                // 18432 (73.7 KB) one-time W
#define ST_F  (KA * 16)                // 9216  (36.9 KB) per-step S++x
#define HS_F  (HT * 17)                // 544   padded h tile
#define RED_F (NWARP * 32 * 16)        // 8192  K-split partials
#define SMEM_FLOATS (WT_F + ST_F + HS_F + RED_F)
#define SMEM_BYTES  (SMEM_FLOATS * 4)  // ~145.5 KB -> 1 CTA/SM

// ---- global scratch (__device__ globals: allocation-free rule) ----
__device__ float g_S[2][H_ * B_];          // double-buffered sigmoid(h)
__device__ float g_xT[T_ * I_ * B_];       // x transposed to [t][i][b]

__device__ __forceinline__ void fma2(unsigned long long &acc,
                                     unsigned long long a,
                                     unsigned long long b) {
    asm("fma.rn.f32x2 %0, %1, %2, %0;" : "+l"(acc) : "l"(a), "l"(b));
}

__device__ __forceinline__ unsigned long long dup2(float v) {
    unsigned long long r;
    asm("mov.b64 %0, {%1, %1};" : "=l"(r) : "f"(v));
    return r;
}

__device__ __forceinline__ float sigmoidf_(float x) {
    return 1.0f / (1.0f + __expf(-x));
}

__global__ void __launch_bounds__(NTHR, 1)
rnn_coop_kernel(const float* __restrict__ x,      // [B,T,I]
                const float* __restrict__ W_in,   // [H,I]
                const float* __restrict__ W_h,    // [H,H]
                const float* __restrict__ sigma,  // [H,T,B]
                const float* __restrict__ h0,     // [H,B]
                float* __restrict__ out)          // [B,T,H] ++ [H,B]
{
    extern __shared__ float sm[];
    float* wtile = sm;                     // [KA][32]  W_aug slice (one-time)
    float* stile = sm + WT_F;              // [KA][16]  staged S ++ x rows
    float* hs    = sm + WT_F + ST_F;       // [32][17]  h tile (padded)
    float* red   = sm + WT_F + ST_F + HS_F;// [16w][32lane][16]
    float* ts    = red;                    // transpose scratch alias

    cg::grid_group grid = cg::this_grid();

    const int tid  = threadIdx.x;
    const int warp = tid >> 5;
    const int lane = tid & 31;
    const int cta  = blockIdx.x;
    const int h0r  = (cta >> 3) * HT;      // 16 h-tiles
    const int b0   = (cta & 7)  * BT;      // 8 b-tiles

    // ---- one-time: wtile[k][h] = W_aug[h0r+h][k]  (4608 float4 tasks)
    #pragma unroll
    for (int it = 0; it < 9; ++it) {
        int idx = it * NTHR + tid;
        int h  = idx & 31;
        int k4 = idx >> 5;                 // 0..143
        float4 w4 = (k4 < 128)
            ? *(const float4*)(W_h  + (size_t)(h0r + h) * H_ + 4 * k4)
            : *(const float4*)(W_in + (size_t)(h0r + h) * I_ + 4 * k4 - 512);
        wtile[(4 * k4 + 0) * 32 + h] = w4.x;   // lane-distinct h: conflict-free
        wtile[(4 * k4 + 1) * 32 + h] = w4.y;
        wtile[(4 * k4 + 2) * 32 + h] = w4.z;
        wtile[(4 * k4 + 3) * 32 + h] = w4.w;
    }

    // ---- one-time: transpose x[B,T,I] -> g_xT[t][i][b] (first 256 threads)
    for (int tile = cta; tile < 8192; tile += NCTA) {
        int tb = tile & 3;
        int ti = (tile >> 2) & 1;
        int tt = tile >> 3;
        if (tid < 256) {
            int row = tid >> 3, c4 = tid & 7;
            float4 v = *(const float4*)(x + (size_t)(tb * 32 + row) * (T_ * I_)
                                          + (size_t)tt * I_ + ti * 32 + 4 * c4);
            ts[(4 * c4 + 0) * 33 + row] = v.x;
            ts[(4 * c4 + 1) * 33 + row] = v.y;
            ts[(4 * c4 + 2) * 33 + row] = v.z;
            ts[(4 * c4 + 3) * 33 + row] = v.w;
        }
        __syncthreads();
        if (tid < 256) {
            int irow = tid >> 3, b4 = tid & 7;
            float4 v;
            v.x = ts[irow * 33 + 4 * b4 + 0];
            v.y = ts[irow * 33 + 4 * b4 + 1];
            v.z = ts[irow * 33 + 4 * b4 + 2];
            v.w = ts[irow * 33 + 4 * b4 + 3];
            __stcg((float4*)(g_xT + ((size_t)tt * I_ + ti * 32 + irow) * B_
                                  + tb * 32 + 4 * b4), v);
        }
        __syncthreads();
    }

    // ---- init h tile + publish sigmoid(h0) into buffer 0
    const int uH = tid >> 4;               // update-map h (0..31)
    const int uB = tid & 15;               // update-map b (0..15)
    {
        float h = h0[(size_t)(h0r + uH) * B_ + b0 + uB];
        hs[uH * 17 + uB] = h;
        __stcg(&g_S[0][(size_t)(h0r + uH) * B_ + b0 + uB], sigmoidf_(h));
    }
    grid.sync();

    const int hgrp = lane >> 2;            // 0..7  -> h base 4*hgrp
    const int bgrp = lane & 3;             // 0..3  -> b base 4*bgrp
    // reduce-phase addressing for this thread's (uH, uB) cell
    const int rlp  = (uH >> 2) * 4 + (uB >> 2);
    const int roff = (uH & 3) * 4 + (uB & 3);

    int p = 0;
    for (int t = 0; t < T_; ++t) {
        // ---- stage stile[576][16]: S rows (.cg) ++ x rows  (2304 float4)
        #pragma unroll
        for (int it = 0; it < 5; ++it) {
            int idx = it * NTHR + tid;
            if (idx < KA * 4) {
                int row = idx >> 2, q = (idx & 3) * 4;
                float4 v = (row < H_)
                    ? __ldcg((const float4*)(g_S[p] + (size_t)row * B_ + b0 + q))
                    : __ldg((const float4*)(g_xT + ((size_t)t * I_ + row - H_) * B_ + b0 + q));
                *(float4*)(stile + row * 16 + q) = v;
            }
        }
        // sigma prefetch for the update phase (latency hidden under GEMM)
        float sgv = __ldg(sigma + ((size_t)(h0r + uH) * T_ + t) * B_ + b0 + uB);
        __syncthreads();

        // ---- GEMM: lane = 4h x 4b; 1 w-LDS.128 + 1 s-LDS.128 + 8 FFMA2 / k
        unsigned long long acc[4][2];
        #pragma unroll
        for (int i = 0; i < 4; ++i) { acc[i][0] = 0ull; acc[i][1] = 0ull; }
        {
            const float* wp = wtile + (KW * warp) * 32 + 4 * hgrp;
            const float* sp = stile + (KW * warp) * 16 + 4 * bgrp;
            #pragma unroll
            for (int j = 0; j < KW; ++j) {
                float4 w4 = *(const float4*)(wp + j * 32);
                ulonglong2 s2 = *(const ulonglong2*)(sp + j * 16);
                unsigned long long wd0 = dup2(w4.x), wd1 = dup2(w4.y);
                unsigned long long wd2 = dup2(w4.z), wd3 = dup2(w4.w);
                fma2(acc[0][0], wd0, s2.x); fma2(acc[0][1], wd0, s2.y);
                fma2(acc[1][0], wd1, s2.x); fma2(acc[1][1], wd1, s2.y);
                fma2(acc[2][0], wd2, s2.x); fma2(acc[2][1], wd2, s2.y);
                fma2(acc[3][0], wd3, s2.x); fma2(acc[3][1], wd3, s2.y);
            }
        }

        // ---- store K-split partials: 64B block per (warp, lane)
        {
            ulonglong2* blk = (ulonglong2*)(red + (warp * 32 + lane) * 16);
            blk[0] = make_ulonglong2(acc[0][0], acc[0][1]);
            blk[1] = make_ulonglong2(acc[1][0], acc[1][1]);
            blk[2] = make_ulonglong2(acc[2][0], acc[2][1]);
            blk[3] = make_ulonglong2(acc[3][0], acc[3][1]);
        }
        __syncthreads();

        // ---- reduce 16 partials + leaky update (1 (h,b) cell per thread)
        {
            float s = 0.f;
            #pragma unroll
            for (int w = 0; w < NWARP; ++w)
                s += red[(w * 32 + rlp) * 16 + roff];
            float hn = C1 * hs[uH * 17 + uB] + C2 * (s + sgv);
            hs[uH * 17 + uB] = hn;
            __stcg(&g_S[1 - p][(size_t)(h0r + uH) * B_ + b0 + uB], sigmoidf_(hn));
        }
        __syncthreads();

        // ---- coalesced out tile [B,T,H]: warp writes 128B contiguous
        {
            int ob = tid >> 5, oh = tid & 31;
            out[((size_t)(b0 + ob) * T_ + t) * H_ + h0r + oh] = hs[oh * 17 + ob];
        }

        grid.sync();
        p ^= 1;
    }

    // ---- h_last [H,B] appended after out [B,T,H]
    out[(size_t)B_ * T_ * H_ + (size_t)(h0r + uH) * B_ + b0 + uB] = hs[uH * 17 + uB];
}

extern "C" void kernel_launch(void* const* d_in, const int* in_sizes, int n_in,
                              void* d_out, int out_size) {
    const float* x    = (const float*)d_in[0];
    const float* W_in = (const float*)d_in[1];
    const float* W_h  = (const float*)d_in[2];
    const float* sg   = (const float*)d_in[3];
    const float* h0   = (const float*)d_in[4];
    float* out = (float*)d_out;

    static int smem_set = 0;
    if (!smem_set) {
        cudaFuncSetAttribute(rnn_coop_kernel,
                             cudaFuncAttributeMaxDynamicSharedMemorySize, SMEM_BYTES);
        smem_set = 1;
    }

    cudaLaunchConfig_t cfg = {};
    cfg.gridDim  = dim3(NCTA, 1, 1);
    cfg.blockDim = dim3(NTHR, 1, 1);
    cfg.dynamicSmemBytes = SMEM_BYTES;
    cfg.stream = 0;
    cudaLaunchAttribute attr[1];
    attr[0].id = cudaLaunchAttributeCooperative;
    attr[0].val.cooperative = 1;
    cfg.attrs = attr;
    cfg.numAttrs = 1;

    cudaLaunchKernelEx(&cfg, rnn_coop_kernel, x, W_in, W_h, sg, h0, out);
}